// round 5
// baseline (speedup 1.0000x reference)
#include <cuda_runtime.h>
#include <math.h>
#include <stdint.h>

// ---------------- problem constants ----------------
#define NROWS  4096
#define DDIM   256
#define KMEM   16384
#define ZCOLS  4096
#define WROWS  (ZCOLS + KMEM)   // 20480
#define LSEQ   256
#define SPLITS 9                // 80 col tiles of 256: 8x9 + 1x8
#define TMR    128
#define TNC    256
#define SA     260              // A stride (words); ==4 mod 32 -> LDS.128 conflict-free
#define SB     36               // B stride (words); ==4 mod 32
#define INV_T  (1.0f/0.07f)
#define LOG2E  1.4426950408889634f
#define LN2F   0.6931471805599453f
#define NEG_BIG (-1.0e30f)

#define SMEM_DYN ((TMR*SA + 2*256*SB) * 4)   // 206,848 B

// ---------------- scratch ----------------
__device__ uint32_t g_wp[(size_t)WROWS * DDIM];   // tf32, chunk-permuted (21 MB)
__device__ float g_pm[SPLITS * NROWS];
__device__ float g_ps[SPLITS * NROWS];
__device__ float g_pp[NROWS];

// ---------------- helpers ----------------
__device__ __forceinline__ uint32_t f2tf(float x) {
    uint32_t r; asm("cvt.rna.tf32.f32 %0, %1;" : "=r"(r) : "f"(x)); return r;
}
__device__ __forceinline__ float ex2f(float x) {
    float r; asm("ex2.approx.f32 %0, %1;" : "=f"(r) : "f"(x)); return r;
}
__device__ __forceinline__ void mma8(float* d,
                                     uint32_t a0, uint32_t a1, uint32_t a2, uint32_t a3,
                                     uint32_t b0, uint32_t b1) {
    asm volatile(
        "mma.sync.aligned.m16n8k8.row.col.f32.tf32.tf32.f32 "
        "{%0,%1,%2,%3}, {%4,%5,%6,%7}, {%8,%9}, {%0,%1,%2,%3};"
        : "+f"(d[0]), "+f"(d[1]), "+f"(d[2]), "+f"(d[3])
        : "r"(a0), "r"(a1), "r"(a2), "r"(a3), "r"(b0), "r"(b1));
}
__device__ __forceinline__ uint32_t smem_u32(const void* p) {
    uint32_t a;
    asm("{ .reg .u64 t; cvta.to.shared.u64 t, %1; cvt.u32.u64 %0, t; }"
        : "=r"(a) : "l"(p));
    return a;
}
__device__ __forceinline__ void cp16(uint32_t dst, const void* src) {
    asm volatile("cp.async.cg.shared.global [%0], [%1], 16;" :: "r"(dst), "l"(src));
}

// ---------------------------------------------------------------------------
// Pre-pass: tf32-convert z||mem with per-32k-chunk word permutation
//   pos(qc,ks,p) = qc*8 + ks*2 + p   for original k = ks*8 + qc + 4p
// One thread per (row, chunk): 8 LDG.128 in, 8 STG.128 out (contiguous).
// ---------------------------------------------------------------------------
__global__ __launch_bounds__(256)
void prep(const float* __restrict__ z, const float* __restrict__ mem) {
    const int idx = blockIdx.x * 256 + threadIdx.x;
    const int row = idx >> 3;
    const int ch  = idx & 7;
    if (row >= WROWS) return;
    const float* src = ((row < ZCOLS) ? (z + (size_t)row * DDIM)
                                      : (mem + (size_t)(row - ZCOLS) * DDIM)) + ch * 32;
    float in[32];
    #pragma unroll
    for (int q = 0; q < 8; ++q)
        *(float4*)(in + q * 4) = *(const float4*)(src + q * 4);
    uint32_t* dst = g_wp + (size_t)row * DDIM + ch * 32;
    #pragma unroll
    for (int u = 0; u < 8; ++u) {
        const int qc = u >> 1, hf = u & 1;
        uint4 o;
        o.x = f2tf(in[(hf * 2 + 0) * 8 + qc]);
        o.y = f2tf(in[(hf * 2 + 0) * 8 + qc + 4]);
        o.z = f2tf(in[(hf * 2 + 1) * 8 + qc]);
        o.w = f2tf(in[(hf * 2 + 1) * 8 + qc + 4]);
        *(uint4*)(dst + u * 4) = o;
    }
}

// ---------------------------------------------------------------------------
// Fused tf32 mma.sync GEMM + online logsumexp.
// 512 threads = 16 warps, 4(M) x 4(N); warp tile 32x64.
// All fragment loads are LDS.128 (two k-steps per load).
// ---------------------------------------------------------------------------
__global__ __launch_bounds__(512, 1)
void lse_mma(const float* __restrict__ zdummy) {
    extern __shared__ uint32_t sm[];
    __shared__ float red_m[16][32];
    __shared__ float red_s[16][32];
    uint32_t* As = sm;                  // [128][SA]
    uint32_t* Bs = sm + TMR * SA;       // 2 x [256][SB]

    const int tid  = threadIdx.x;
    const int wid  = tid >> 5;
    const int lane = tid & 31;
    const int wm   = wid >> 2;          // 0..3 (M)
    const int wn   = wid & 3;           // 0..3 (N)
    const int qr   = lane >> 2;
    const int qc   = lane & 3;
    const int m0   = blockIdx.x * TMR;
    const int s    = blockIdx.y;
    const int lo   = s * 9;
    const int nt   = (s < 8) ? 9 : 8;

    // ---- A tile: verbatim copy of permuted tf32 rows m0..m0+127 ----
    #pragma unroll 4
    for (int it = 0; it < 16; ++it) {
        int idx = it * 512 + tid;           // uint4 index 0..8191
        int m   = idx >> 6;
        int kq  = (idx & 63) << 2;
        uint4 v = *(const uint4*)(g_wp + (size_t)(m0 + m) * DDIM + kq);
        *(uint4*)(As + m * SA + kq) = v;
    }
    __syncthreads();

    float rm[4], rs[4];
    #pragma unroll
    for (int i = 0; i < 4; ++i) { rm[i] = NEG_BIG; rs[i] = 0.0f; }

    const uint32_t bs_base = smem_u32(Bs);
    const float Cs = INV_T * LOG2E;

    // prologue: tile lo, chunk 0 -> buf 0
    {
        const int c0 = lo * TNC;
        #pragma unroll
        for (int it = 0; it < 4; ++it) {
            int idx = it * 512 + tid;       // uint4 idx within 256x32 chunk
            int n   = idx >> 3;
            int kq  = (idx & 7) << 2;
            cp16(bs_base + (uint32_t)((n * SB + kq) << 2),
                 g_wp + (size_t)(c0 + n) * DDIM + kq);
        }
        asm volatile("cp.async.commit_group;" ::: "memory");
    }

    #pragma unroll 1
    for (int ti = 0; ti < nt; ++ti) {
        const int  c0 = (lo + ti) * TNC;
        const bool zp = (c0 < ZCOLS);

        float acc[2][8][4];
        #pragma unroll
        for (int a = 0; a < 2; ++a)
            #pragma unroll
            for (int b = 0; b < 8; ++b)
                #pragma unroll
                for (int c = 0; c < 4; ++c) acc[a][b][c] = 0.0f;

        #pragma unroll 1
        for (int kc = 0; kc < 8; ++kc) {
            const int cur = kc & 1;
            if (kc < 7) {
                const int nb = 1 - cur;
                #pragma unroll
                for (int it = 0; it < 4; ++it) {
                    int idx = it * 512 + tid;
                    int n   = idx >> 3;
                    int kq  = (idx & 7) << 2;
                    cp16(bs_base + (uint32_t)((((nb << 8) + n) * SB + kq) << 2),
                         g_wp + (size_t)(c0 + n) * DDIM + (kc + 1) * 32 + kq);
                }
                asm volatile("cp.async.commit_group;" ::: "memory");
                asm volatile("cp.async.wait_group 1;" ::: "memory");
            } else {
                asm volatile("cp.async.wait_group 0;" ::: "memory");
            }
            __syncthreads();

            const uint32_t* Bc = Bs + cur * 256 * SB;
            #pragma unroll
            for (int hf = 0; hf < 2; ++hf) {
                const int ao = kc * 32 + qc * 8 + hf * 4;
                uint4 aL[2], aH[2], bq[8];
                #pragma unroll
                for (int mi = 0; mi < 2; ++mi) {
                    const int r = wm * 32 + mi * 16 + qr;
                    aL[mi] = *(const uint4*)(As + r * SA + ao);
                    aH[mi] = *(const uint4*)(As + (r + 8) * SA + ao);
                }
                const int bo = qc * 8 + hf * 4;
                #pragma unroll
                for (int ni = 0; ni < 8; ++ni) {
                    const int n = wn * 64 + ni * 8 + qr;
                    bq[ni] = *(const uint4*)(Bc + n * SB + bo);
                }
                #pragma unroll
                for (int mi = 0; mi < 2; ++mi)
                    #pragma unroll
                    for (int ni = 0; ni < 8; ++ni) {
                        mma8(acc[mi][ni], aL[mi].x, aH[mi].x, aL[mi].y, aH[mi].y,
                             bq[ni].x, bq[ni].y);
                        mma8(acc[mi][ni], aL[mi].z, aH[mi].z, aL[mi].w, aH[mi].w,
                             bq[ni].z, bq[ni].w);
                    }
            }
            __syncthreads();
        }

        // prefetch next tile's chunk 0 (hidden under the epilogue)
        if (ti + 1 < nt) {
            const int c1 = (lo + ti + 1) * TNC;
            #pragma unroll
            for (int it = 0; it < 4; ++it) {
                int idx = it * 512 + tid;
                int n   = idx >> 3;
                int kq  = (idx & 7) << 2;
                cp16(bs_base + (uint32_t)((n * SB + kq) << 2),
                     g_wp + (size_t)(c1 + n) * DDIM + kq);
            }
            asm volatile("cp.async.commit_group;" ::: "memory");
        }

        // ---- flash-LSE epilogue ----
        const bool dflag = zp && (c0 == (m0 & ~(TNC - 1)));
        #pragma unroll
        for (int mi = 0; mi < 2; ++mi) {
            #pragma unroll
            for (int h = 0; h < 2; ++h) {
                const int lr   = wm * 32 + mi * 16 + h * 8 + qr;
                const int grow = m0 + lr;
                float v[16];
                float mx = NEG_BIG;
                #pragma unroll
                for (int ni = 0; ni < 8; ++ni) {
                    #pragma unroll
                    for (int c = 0; c < 2; ++c) {
                        float x = acc[mi][ni][h * 2 + c] * Cs;
                        if (dflag) {
                            const int gcol = c0 + wn * 64 + ni * 8 + 2 * qc + c;
                            if (gcol == grow) x = NEG_BIG;
                        }
                        v[ni * 2 + c] = x;
                        mx = fmaxf(mx, x);
                    }
                }
                mx = fmaxf(mx, __shfl_xor_sync(0xffffffffu, mx, 1));
                mx = fmaxf(mx, __shfl_xor_sync(0xffffffffu, mx, 2));
                float sc = 0.0f;
                #pragma unroll
                for (int j = 0; j < 16; ++j) sc += ex2f(v[j] - mx);
                sc += __shfl_xor_sync(0xffffffffu, sc, 1);
                sc += __shfl_xor_sync(0xffffffffu, sc, 2);
                const int ri = mi * 2 + h;
                const float mn = fmaxf(rm[ri], mx);
                rs[ri] = rs[ri] * ex2f(rm[ri] - mn) + sc * ex2f(mx - mn);
                rm[ri] = mn;
            }
        }
    }

    // ---- cross-warp (N-dim) merge ----
    if (qc == 0) {
        #pragma unroll
        for (int mi = 0; mi < 2; ++mi)
            #pragma unroll
            for (int h = 0; h < 2; ++h) {
                const int lrw = mi * 16 + h * 8 + qr;   // 0..31
                red_m[wid][lrw] = rm[mi * 2 + h];
                red_s[wid][lrw] = rs[mi * 2 + h];
            }
    }
    __syncthreads();
    if (tid < 128) {
        const int wmm = tid >> 5, ri = tid & 31;
        float m = red_m[wmm * 4][ri];
        #pragma unroll
        for (int w = 1; w < 4; ++w) m = fmaxf(m, red_m[wmm * 4 + w][ri]);
        float ss = 0.0f;
        #pragma unroll
        for (int w = 0; w < 4; ++w)
            ss += red_s[wmm * 4 + w][ri] * ex2f(red_m[wmm * 4 + w][ri] - m);
        g_pm[s * NROWS + m0 + tid] = m;
        g_ps[s * NROWS + m0 + tid] = ss;
    }
}

// ---------------------------------------------------------------------------
__global__ void lse_finalize(const float* __restrict__ z) {
    const int i = blockIdx.x * blockDim.x + threadIdx.x;
    if (i >= NROWS) return;

    float m = g_pm[i];
    #pragma unroll
    for (int s2 = 1; s2 < SPLITS; ++s2)
        m = fmaxf(m, g_pm[s2 * NROWS + i]);
    float ss = 0.0f;
    #pragma unroll
    for (int s2 = 0; s2 < SPLITS; ++s2)
        ss += g_ps[s2 * NROWS + i] * ex2f(g_pm[s2 * NROWS + i] - m);
    const float lse = (m + log2f(ss)) * LN2F;

    const bool valid = (i < NROWS - 1) && ((i & (LSEQ - 1)) != (LSEQ - 1));
    float pp = 0.0f;
    if (valid) {
        const float4* a = (const float4*)(z + (size_t)i * DDIM);
        const float4* b = (const float4*)(z + (size_t)(i + 1) * DDIM);
        float d0 = 0.0f;
        #pragma unroll 8
        for (int k = 0; k < DDIM / 4; ++k) {
            float4 x = a[k], y = b[k];
            d0 = fmaf(x.x, y.x, d0);
            d0 = fmaf(x.y, y.y, d0);
            d0 = fmaf(x.z, y.z, d0);
            d0 = fmaf(x.w, y.w, d0);
        }
        pp = lse - d0 * INV_T;
    }
    g_pp[i] = pp;
}

__global__ void lse_reduce(float* __restrict__ out) {
    __shared__ float sh[256];
    const int tid = threadIdx.x;
    float v = 0.0f;
    for (int i = tid; i < NROWS; i += 256) v += g_pp[i];
    sh[tid] = v;
    __syncthreads();
    for (int o = 128; o > 0; o >>= 1) {
        if (tid < o) sh[tid] += sh[tid + o];
        __syncthreads();
    }
    if (tid == 0) out[0] = sh[0] * (1.0f / 4080.0f);
}

// ---------------------------------------------------------------------------
extern "C" void kernel_launch(void* const* d_in, const int* in_sizes, int n_in,
                              void* d_out, int out_size) {
    const float* z   = nullptr;
    const float* mem = nullptr;
    for (int i = 0; i < n_in; ++i) {
        if (in_sizes[i] == NROWS * DDIM && !z)   z   = (const float*)d_in[i];
        if (in_sizes[i] == KMEM * DDIM  && !mem) mem = (const float*)d_in[i];
    }
    if (!z)   z   = (const float*)d_in[0];
    if (!mem) mem = (const float*)d_in[2];

    cudaFuncSetAttribute(lse_mma, cudaFuncAttributeMaxDynamicSharedMemorySize,
                         SMEM_DYN);
    prep<<<(WROWS * 8 + 255) / 256, 256>>>(z, mem);
    lse_mma<<<dim3(32, SPLITS), 512, SMEM_DYN>>>(z);
    lse_finalize<<<32, 128>>>(z);
    lse_reduce<<<1, 256>>>((float*)d_out);
}

// round 6
// speedup vs baseline: 1.2816x; 1.2816x over previous
#include <cuda_runtime.h>
#include <math.h>
#include <stdint.h>

// ---------------- problem constants ----------------
#define NROWS  4096
#define DDIM   256
#define KMEM   16384
#define ZCOLS  4096
#define WROWS  (ZCOLS + KMEM)   // 20480
#define LSEQ   256
#define SPLITS 9                // 80 col tiles of 256: 8x9 + 1x8
#define TMR    128
#define TNC    256
#define SA     260              // A smem stride (words); ==4 mod 32
#define INV_T  (1.0f/0.07f)
#define LOG2E  1.4426950408889634f
#define LN2F   0.6931471805599453f
#define NEG_BIG (-1.0e30f)

#define SMEM_DYN (TMR * SA * 4)   // 133,120 B (A tile only)

// ---------------- scratch ----------------
__device__ uint32_t g_wp[(size_t)WROWS * DDIM];   // tf32, chunk-permuted (21 MB)
__device__ float g_pm[SPLITS * NROWS];
__device__ float g_ps[SPLITS * NROWS];
__device__ float g_bs[32];

// ---------------- helpers ----------------
__device__ __forceinline__ uint32_t f2tf(float x) {
    uint32_t r; asm("cvt.rna.tf32.f32 %0, %1;" : "=r"(r) : "f"(x)); return r;
}
__device__ __forceinline__ float ex2f(float x) {
    float r; asm("ex2.approx.f32 %0, %1;" : "=f"(r) : "f"(x)); return r;
}
__device__ __forceinline__ void mma8(float* d,
                                     uint32_t a0, uint32_t a1, uint32_t a2, uint32_t a3,
                                     uint32_t b0, uint32_t b1) {
    asm volatile(
        "mma.sync.aligned.m16n8k8.row.col.f32.tf32.tf32.f32 "
        "{%0,%1,%2,%3}, {%4,%5,%6,%7}, {%8,%9}, {%0,%1,%2,%3};"
        : "+f"(d[0]), "+f"(d[1]), "+f"(d[2]), "+f"(d[3])
        : "r"(a0), "r"(a1), "r"(a2), "r"(a3), "r"(b0), "r"(b1));
}

// ---------------------------------------------------------------------------
// Pre-pass: tf32-convert z||mem with per-32k-chunk word permutation
//   pos(qc,ks,p) = qc*8 + ks*2 + p   for original k = ks*8 + qc + 4p
// ---------------------------------------------------------------------------
__global__ __launch_bounds__(256)
void prep(const float* __restrict__ z, const float* __restrict__ mem) {
    const int idx = blockIdx.x * 256 + threadIdx.x;
    const int row = idx >> 3;
    const int ch  = idx & 7;
    if (row >= WROWS) return;
    const float* src = ((row < ZCOLS) ? (z + (size_t)row * DDIM)
                                      : (mem + (size_t)(row - ZCOLS) * DDIM)) + ch * 32;
    float in[32];
    #pragma unroll
    for (int q = 0; q < 8; ++q)
        *(float4*)(in + q * 4) = *(const float4*)(src + q * 4);
    uint32_t* dst = g_wp + (size_t)row * DDIM + ch * 32;
    #pragma unroll
    for (int u = 0; u < 8; ++u) {
        const int qc = u >> 1, hf = u & 1;
        uint4 o;
        o.x = f2tf(in[(hf * 2 + 0) * 8 + qc]);
        o.y = f2tf(in[(hf * 2 + 0) * 8 + qc + 4]);
        o.z = f2tf(in[(hf * 2 + 1) * 8 + qc]);
        o.w = f2tf(in[(hf * 2 + 1) * 8 + qc + 4]);
        *(uint4*)(dst + u * 4) = o;
    }
}

// ---------------------------------------------------------------------------
// Fused tf32 mma.sync GEMM + online logsumexp.
// 256 threads = 8 warps, 2(M) x 4(N); warp tile 64x64.
// A resident in SMEM (one barrier total); B fragments streamed per-warp via
// LDG.128 from the permuted global buffer with a register double buffer.
// NO barriers in the k-loop or tile loop.
// ---------------------------------------------------------------------------
__global__ __launch_bounds__(256, 1)
void lse_mma() {
    extern __shared__ uint32_t As[];    // [128][SA]
    __shared__ float red_m[8][64];
    __shared__ float red_s[8][64];

    const int tid  = threadIdx.x;
    const int wid  = tid >> 5;
    const int lane = tid & 31;
    const int wm   = wid >> 2;          // 0..1 (M)
    const int wn   = wid & 3;           // 0..3 (N)
    const int qr   = lane >> 2;         // 0..7
    const int qc   = lane & 3;          // 0..3
    const int m0   = blockIdx.x * TMR;
    const int s    = blockIdx.y;
    const int lo   = s * 9;
    const int nt   = (s < 8) ? 9 : 8;

    // ---- A tile: verbatim copy of permuted tf32 rows m0..m0+127 ----
    #pragma unroll 4
    for (int it = 0; it < 32; ++it) {
        int idx = it * 256 + tid;           // uint4 index 0..8191
        int m   = idx >> 6;
        int kq  = (idx & 63) << 2;
        uint4 v = *(const uint4*)(g_wp + (size_t)(m0 + m) * DDIM + kq);
        *(uint4*)(As + m * SA + kq) = v;
    }
    __syncthreads();                        // the ONLY block barrier before the end

    float rm[8], rs[8];
    #pragma unroll
    for (int i = 0; i < 8; ++i) { rm[i] = NEG_BIG; rs[i] = 0.0f; }

    const float Cs = INV_T * LOG2E;

    #pragma unroll 1
    for (int ti = 0; ti < nt; ++ti) {
        const int  c0 = (lo + ti) * TNC;
        const bool zp = (c0 < ZCOLS);

        // per-warp B base: row (c0 + wn*64 + qr), word qc*8 of each chunk
        const uint32_t* bp = g_wp + (size_t)(c0 + wn * 64 + qr) * DDIM + qc * 8;

        float acc[4][8][4];
        #pragma unroll
        for (int a = 0; a < 4; ++a)
            #pragma unroll
            for (int b = 0; b < 8; ++b)
                #pragma unroll
                for (int c = 0; c < 4; ++c) acc[a][b][c] = 0.0f;

        uint4 bq[2][8];
        #pragma unroll
        for (int ni = 0; ni < 8; ++ni)      // prologue: (kc=0, hf=0)
            bq[0][ni] = *(const uint4*)(bp + ni * 8 * DDIM);

        #pragma unroll 2
        for (int kc = 0; kc < 8; ++kc) {
            #pragma unroll
            for (int hf = 0; hf < 2; ++hf) {
                const int idx = kc * 2 + hf;
                const int cur = idx & 1;
                if (idx < 15) {             // prefetch next half-chunk
                    const int nk = (idx + 1) >> 1;
                    const int nh = (idx + 1) & 1;
                    const int no = nk * 32 + nh * 4;
                    #pragma unroll
                    for (int ni = 0; ni < 8; ++ni)
                        bq[cur ^ 1][ni] = *(const uint4*)(bp + ni * 8 * DDIM + no);
                }
                const int ao = kc * 32 + qc * 8 + hf * 4;
                uint4 aL[4], aH[4];
                #pragma unroll
                for (int mi = 0; mi < 4; ++mi) {
                    const int r = wm * 64 + mi * 16 + qr;
                    aL[mi] = *(const uint4*)(As + r * SA + ao);
                    aH[mi] = *(const uint4*)(As + (r + 8) * SA + ao);
                }
                #pragma unroll
                for (int mi = 0; mi < 4; ++mi)
                    #pragma unroll
                    for (int ni = 0; ni < 8; ++ni) {
                        mma8(acc[mi][ni], aL[mi].x, aH[mi].x, aL[mi].y, aH[mi].y,
                             bq[cur][ni].x, bq[cur][ni].y);
                        mma8(acc[mi][ni], aL[mi].z, aH[mi].z, aL[mi].w, aH[mi].w,
                             bq[cur][ni].z, bq[cur][ni].w);
                    }
            }
        }

        // ---- flash-LSE epilogue (per-warp, no barriers) ----
        const bool dflag = zp && (c0 == (m0 & ~(TNC - 1)));
        #pragma unroll
        for (int mi = 0; mi < 4; ++mi) {
            #pragma unroll
            for (int h = 0; h < 2; ++h) {
                const int lr   = wm * 64 + mi * 16 + h * 8 + qr;
                const int grow = m0 + lr;
                float v[16];
                float mx = NEG_BIG;
                #pragma unroll
                for (int ni = 0; ni < 8; ++ni) {
                    #pragma unroll
                    for (int c = 0; c < 2; ++c) {
                        float x = acc[mi][ni][h * 2 + c] * Cs;
                        if (dflag) {
                            const int gcol = c0 + wn * 64 + ni * 8 + 2 * qc + c;
                            if (gcol == grow) x = NEG_BIG;
                        }
                        v[ni * 2 + c] = x;
                        mx = fmaxf(mx, x);
                    }
                }
                mx = fmaxf(mx, __shfl_xor_sync(0xffffffffu, mx, 1));
                mx = fmaxf(mx, __shfl_xor_sync(0xffffffffu, mx, 2));
                float sc = 0.0f;
                #pragma unroll
                for (int j = 0; j < 16; ++j) sc += ex2f(v[j] - mx);
                sc += __shfl_xor_sync(0xffffffffu, sc, 1);
                sc += __shfl_xor_sync(0xffffffffu, sc, 2);
                const int ri = mi * 2 + h;
                const float mn = fmaxf(rm[ri], mx);
                rs[ri] = rs[ri] * ex2f(rm[ri] - mn) + sc * ex2f(mx - mn);
                rm[ri] = mn;
            }
        }
    }

    // ---- cross-warp (N-dim) merge via smem ----
    if (qc == 0) {
        #pragma unroll
        for (int mi = 0; mi < 4; ++mi)
            #pragma unroll
            for (int h = 0; h < 2; ++h) {
                const int lrw = mi * 16 + h * 8 + qr;
                red_m[wid][lrw] = rm[mi * 2 + h];
                red_s[wid][lrw] = rs[mi * 2 + h];
            }
    }
    __syncthreads();
    if (tid < 128) {
        const int wmm = tid >> 6, ri = tid & 63;
        float m = red_m[wmm * 4][ri];
        #pragma unroll
        for (int w = 1; w < 4; ++w) m = fmaxf(m, red_m[wmm * 4 + w][ri]);
        float ss = 0.0f;
        #pragma unroll
        for (int w = 0; w < 4; ++w)
            ss += red_s[wmm * 4 + w][ri] * ex2f(red_m[wmm * 4 + w][ri] - m);
        g_pm[s * NROWS + m0 + tid] = m;
        g_ps[s * NROWS + m0 + tid] = ss;
    }
}

// ---------------------------------------------------------------------------
// Combine split partials -> lse -> per-pair term -> per-block partial sum.
// 32 blocks x 128 threads; block b owns rows [b*128, b*128+128).
// ---------------------------------------------------------------------------
__global__ void lse_finalize(const float* __restrict__ z) {
    __shared__ float sh[128];
    const int i = blockIdx.x * 128 + threadIdx.x;

    float m = g_pm[i];
    #pragma unroll
    for (int s2 = 1; s2 < SPLITS; ++s2)
        m = fmaxf(m, g_pm[s2 * NROWS + i]);
    float ss = 0.0f;
    #pragma unroll
    for (int s2 = 0; s2 < SPLITS; ++s2)
        ss += g_ps[s2 * NROWS + i] * ex2f(g_pm[s2 * NROWS + i] - m);
    const float lse = (m + log2f(ss)) * LN2F;

    const bool valid = (i < NROWS - 1) && ((i & (LSEQ - 1)) != (LSEQ - 1));
    float pp = 0.0f;
    if (valid) {
        const float4* a = (const float4*)(z + (size_t)i * DDIM);
        const float4* b = (const float4*)(z + (size_t)(i + 1) * DDIM);
        float d0 = 0.0f;
        #pragma unroll 8
        for (int k = 0; k < DDIM / 4; ++k) {
            float4 x = a[k], y = b[k];
            d0 = fmaf(x.x, y.x, d0);
            d0 = fmaf(x.y, y.y, d0);
            d0 = fmaf(x.z, y.z, d0);
            d0 = fmaf(x.w, y.w, d0);
        }
        pp = lse - d0 * INV_T;
    }

    sh[threadIdx.x] = pp;
    __syncthreads();
    #pragma unroll
    for (int o = 64; o > 0; o >>= 1) {
        if (threadIdx.x < o) sh[threadIdx.x] += sh[threadIdx.x + o];
        __syncthreads();
    }
    if (threadIdx.x == 0) g_bs[blockIdx.x] = sh[0];
}

__global__ void lse_reduce(float* __restrict__ out) {
    const int t = threadIdx.x;
    float v = (t < 32) ? g_bs[t] : 0.0f;
    #pragma unroll
    for (int o = 16; o > 0; o >>= 1)
        v += __shfl_xor_sync(0xffffffffu, v, o);
    if (t == 0) out[0] = v * (1.0f / 4080.0f);
}

// ---------------------------------------------------------------------------
extern "C" void kernel_launch(void* const* d_in, const int* in_sizes, int n_in,
                              void* d_out, int out_size) {
    const float* z   = nullptr;
    const float* mem = nullptr;
    for (int i = 0; i < n_in; ++i) {
        if (in_sizes[i] == NROWS * DDIM && !z)   z   = (const float*)d_in[i];
        if (in_sizes[i] == KMEM * DDIM  && !mem) mem = (const float*)d_in[i];
    }
    if (!z)   z   = (const float*)d_in[0];
    if (!mem) mem = (const float*)d_in[2];

    cudaFuncSetAttribute(lse_mma, cudaFuncAttributeMaxDynamicSharedMemorySize,
                         SMEM_DYN);
    prep<<<(WROWS * 8 + 255) / 256, 256>>>(z, mem);
    lse_mma<<<dim3(32, SPLITS), 256, SMEM_DYN>>>();
    lse_finalize<<<32, 128>>>(z);
    lse_reduce<<<1, 32>>>((float*)d_out);
}

// round 7
// speedup vs baseline: 1.2838x; 1.0018x over previous
#include <cuda_runtime.h>
#include <math.h>
#include <stdint.h>

// ---------------- problem constants ----------------
#define NROWS  4096
#define DDIM   256
#define KMEM   16384
#define ZCOLS  4096
#define WROWS  (ZCOLS + KMEM)   // 20480
#define LSEQ   256
#define SPLITS 9                // 80 col tiles of 256: 8x9 + 1x8
#define TMR    128
#define TNC    256
#define SA     260              // A smem stride (words); ==4 mod 32
#define INV_T  (1.0f/0.07f)
#define LOG2E  1.4426950408889634f
#define LN2F   0.6931471805599453f
#define NEG_BIG (-1.0e30f)

#define SMEM_DYN (TMR * SA * 4)   // 133,120 B (A tile only)

// ---------------- scratch ----------------
// tf32, chunk-permuted for sector-perfect B loads:
//   word-in-chunk = hf*16 + qc*4 + e   (fragment {k(2hf,qc), k(2hf,qc+4),
//                                       k(2hf+1,qc), k(2hf+1,qc+4)})
__device__ uint32_t g_wp[(size_t)WROWS * DDIM];
__device__ float g_pm[SPLITS * NROWS];
__device__ float g_ps[SPLITS * NROWS];
__device__ float g_bs[32];

// ---------------- helpers ----------------
__device__ __forceinline__ uint32_t f2tf(float x) {
    uint32_t r; asm("cvt.rna.tf32.f32 %0, %1;" : "=r"(r) : "f"(x)); return r;
}
__device__ __forceinline__ float ex2f(float x) {
    float r; asm("ex2.approx.f32 %0, %1;" : "=f"(r) : "f"(x)); return r;
}
__device__ __forceinline__ void mma8(float* d,
                                     uint32_t a0, uint32_t a1, uint32_t a2, uint32_t a3,
                                     uint32_t b0, uint32_t b1) {
    asm volatile(
        "mma.sync.aligned.m16n8k8.row.col.f32.tf32.tf32.f32 "
        "{%0,%1,%2,%3}, {%4,%5,%6,%7}, {%8,%9}, {%0,%1,%2,%3};"
        : "+f"(d[0]), "+f"(d[1]), "+f"(d[2]), "+f"(d[3])
        : "r"(a0), "r"(a1), "r"(a2), "r"(a3), "r"(b0), "r"(b1));
}

// ---------------------------------------------------------------------------
// Pre-pass: tf32-convert z||mem; per-32k-chunk layout = [hf][qc][4 words]
// so that a half-chunk's 4 lane-fragments are 64B-contiguous per row.
// ---------------------------------------------------------------------------
__global__ __launch_bounds__(256)
void prep(const float* __restrict__ z, const float* __restrict__ mem) {
    const int idx = blockIdx.x * 256 + threadIdx.x;
    const int row = idx >> 3;
    const int ch  = idx & 7;
    if (row >= WROWS) return;
    const float* src = ((row < ZCOLS) ? (z + (size_t)row * DDIM)
                                      : (mem + (size_t)(row - ZCOLS) * DDIM)) + ch * 32;
    float in[32];
    #pragma unroll
    for (int q = 0; q < 8; ++q)
        *(float4*)(in + q * 4) = *(const float4*)(src + q * 4);
    uint32_t* dst = g_wp + (size_t)row * DDIM + ch * 32;
    #pragma unroll
    for (int u = 0; u < 8; ++u) {
        const int hf = u >> 2, qc = u & 3;          // NEW: hf-major, qc contiguous
        uint4 o;
        o.x = f2tf(in[(hf * 2 + 0) * 8 + qc]);
        o.y = f2tf(in[(hf * 2 + 0) * 8 + qc + 4]);
        o.z = f2tf(in[(hf * 2 + 1) * 8 + qc]);
        o.w = f2tf(in[(hf * 2 + 1) * 8 + qc + 4]);
        *(uint4*)(dst + u * 4) = o;
    }
}

// ---------------------------------------------------------------------------
// Fused tf32 mma.sync GEMM + online logsumexp.
// 256 threads = 8 warps, 2(M) x 4(N); warp tile 64x64.
// A resident in SMEM (R6 layout via quad remap at copy); B fragments streamed
// per-warp via sector-perfect LDG.128 with a register double buffer.
// NO barriers in the k-loop or tile loop.
// ---------------------------------------------------------------------------
__global__ __launch_bounds__(256, 1)
void lse_mma() {
    extern __shared__ uint32_t As[];    // [128][SA], layout: quad d = qc*2+hf
    __shared__ float red_m[8][64];
    __shared__ float red_s[8][64];

    const int tid  = threadIdx.x;
    const int wid  = tid >> 5;
    const int lane = tid & 31;
    const int wm   = wid >> 2;          // 0..1 (M)
    const int wn   = wid & 3;           // 0..3 (N)
    const int qr   = lane >> 2;         // 0..7
    const int qc   = lane & 3;          // 0..3
    const int m0   = blockIdx.x * TMR;
    const int s    = blockIdx.y;
    const int lo   = s * 9;
    const int nt   = (s < 8) ? 9 : 8;

    // ---- A tile copy with quad remap: smem quad d holds g_wp quad
    //      src_d = ((d&1)<<2) | (d>>1)   (old layout d = qc*2+hf) ----
    #pragma unroll 4
    for (int it = 0; it < 32; ++it) {
        int idx = it * 256 + tid;           // uint4 index 0..8191
        int m   = idx >> 6;
        int kq  = idx & 63;                 // dest quad within row
        int d   = kq & 7;
        int sq  = (kq & ~7) | (((d & 1) << 2) | (d >> 1));
        uint4 v = *(const uint4*)(g_wp + (size_t)(m0 + m) * DDIM + sq * 4);
        *(uint4*)(As + m * SA + kq * 4) = v;
    }
    __syncthreads();                        // the ONLY barrier before the end

    float rm[8], rs[8];
    #pragma unroll
    for (int i = 0; i < 8; ++i) { rm[i] = NEG_BIG; rs[i] = 0.0f; }

    const float Cs = INV_T * LOG2E;

    #pragma unroll 1
    for (int ti = 0; ti < nt; ++ti) {
        const int  c0 = (lo + ti) * TNC;
        const bool zp = (c0 < ZCOLS);

        // per-warp B base: row (c0 + wn*64 + qr), lane fragment at word qc*4
        const uint32_t* bp = g_wp + (size_t)(c0 + wn * 64 + qr) * DDIM + qc * 4;

        float acc[4][8][4];
        #pragma unroll
        for (int a = 0; a < 4; ++a)
            #pragma unroll
            for (int b = 0; b < 8; ++b)
                #pragma unroll
                for (int c = 0; c < 4; ++c) acc[a][b][c] = 0.0f;

        uint4 bq[2][8];
        #pragma unroll
        for (int ni = 0; ni < 8; ++ni)      // prologue: (kc=0, hf=0)
            bq[0][ni] = *(const uint4*)(bp + ni * 8 * DDIM);

        #pragma unroll 2
        for (int kc = 0; kc < 8; ++kc) {
            #pragma unroll
            for (int hf = 0; hf < 2; ++hf) {
                const int idx = kc * 2 + hf;
                const int cur = idx & 1;
                if (idx < 15) {             // prefetch next half-chunk
                    const int nk = (idx + 1) >> 1;
                    const int nh = (idx + 1) & 1;
                    const int no = nk * 32 + nh * 16;
                    #pragma unroll
                    for (int ni = 0; ni < 8; ++ni)
                        bq[cur ^ 1][ni] = *(const uint4*)(bp + ni * 8 * DDIM + no);
                }
                const int ao = kc * 32 + qc * 8 + hf * 4;   // A smem layout
                uint4 aL[4], aH[4];
                #pragma unroll
                for (int mi = 0; mi < 4; ++mi) {
                    const int r = wm * 64 + mi * 16 + qr;
                    aL[mi] = *(const uint4*)(As + r * SA + ao);
                    aH[mi] = *(const uint4*)(As + (r + 8) * SA + ao);
                }
                #pragma unroll
                for (int mi = 0; mi < 4; ++mi)
                    #pragma unroll
                    for (int ni = 0; ni < 8; ++ni) {
                        mma8(acc[mi][ni], aL[mi].x, aH[mi].x, aL[mi].y, aH[mi].y,
                             bq[cur][ni].x, bq[cur][ni].y);
                        mma8(acc[mi][ni], aL[mi].z, aH[mi].z, aL[mi].w, aH[mi].w,
                             bq[cur][ni].z, bq[cur][ni].w);
                    }
            }
        }

        // ---- flash-LSE epilogue (per-warp, no barriers) ----
        const bool dflag = zp && (c0 == (m0 & ~(TNC - 1)));
        #pragma unroll
        for (int mi = 0; mi < 4; ++mi) {
            #pragma unroll
            for (int h = 0; h < 2; ++h) {
                const int lr   = wm * 64 + mi * 16 + h * 8 + qr;
                const int grow = m0 + lr;
                float v[16];
                float mx = NEG_BIG;
                #pragma unroll
                for (int ni = 0; ni < 8; ++ni) {
                    #pragma unroll
                    for (int c = 0; c < 2; ++c) {
                        float x = acc[mi][ni][h * 2 + c] * Cs;
                        if (dflag) {
                            const int gcol = c0 + wn * 64 + ni * 8 + 2 * qc + c;
                            if (gcol == grow) x = NEG_BIG;
                        }
                        v[ni * 2 + c] = x;
                        mx = fmaxf(mx, x);
                    }
                }
                mx = fmaxf(mx, __shfl_xor_sync(0xffffffffu, mx, 1));
                mx = fmaxf(mx, __shfl_xor_sync(0xffffffffu, mx, 2));
                float sc = 0.0f;
                #pragma unroll
                for (int j = 0; j < 16; ++j) sc += ex2f(v[j] - mx);
                sc += __shfl_xor_sync(0xffffffffu, sc, 1);
                sc += __shfl_xor_sync(0xffffffffu, sc, 2);
                const int ri = mi * 2 + h;
                const float mn = fmaxf(rm[ri], mx);
                rs[ri] = rs[ri] * ex2f(rm[ri] - mn) + sc * ex2f(mx - mn);
                rm[ri] = mn;
            }
        }
    }

    // ---- cross-warp (N-dim) merge via smem ----
    if (qc == 0) {
        #pragma unroll
        for (int mi = 0; mi < 4; ++mi)
            #pragma unroll
            for (int h = 0; h < 2; ++h) {
                const int lrw = mi * 16 + h * 8 + qr;
                red_m[wid][lrw] = rm[mi * 2 + h];
                red_s[wid][lrw] = rs[mi * 2 + h];
            }
    }
    __syncthreads();
    if (tid < 128) {
        const int wmm = tid >> 6, ri = tid & 63;
        float m = red_m[wmm * 4][ri];
        #pragma unroll
        for (int w = 1; w < 4; ++w) m = fmaxf(m, red_m[wmm * 4 + w][ri]);
        float ss = 0.0f;
        #pragma unroll
        for (int w = 0; w < 4; ++w)
            ss += red_s[wmm * 4 + w][ri] * ex2f(red_m[wmm * 4 + w][ri] - m);
        g_pm[s * NROWS + m0 + tid] = m;
        g_ps[s * NROWS + m0 + tid] = ss;
    }
}

// ---------------------------------------------------------------------------
__global__ void lse_finalize(const float* __restrict__ z) {
    __shared__ float sh[128];
    const int i = blockIdx.x * 128 + threadIdx.x;

    float m = g_pm[i];
    #pragma unroll
    for (int s2 = 1; s2 < SPLITS; ++s2)
        m = fmaxf(m, g_pm[s2 * NROWS + i]);
    float ss = 0.0f;
    #pragma unroll
    for (int s2 = 0; s2 < SPLITS; ++s2)
        ss += g_ps[s2 * NROWS + i] * ex2f(g_pm[s2 * NROWS + i] - m);
    const float lse = (m + log2f(ss)) * LN2F;

    const bool valid = (i < NROWS - 1) && ((i & (LSEQ - 1)) != (LSEQ - 1));
    float pp = 0.0f;
    if (valid) {
        const float4* a = (const float4*)(z + (size_t)i * DDIM);
        const float4* b = (const float4*)(z + (size_t)(i + 1) * DDIM);
        float d0 = 0.0f;
        #pragma unroll 8
        for (int k = 0; k < DDIM / 4; ++k) {
            float4 x = a[k], y = b[k];
            d0 = fmaf(x.x, y.x, d0);
            d0 = fmaf(x.y, y.y, d0);
            d0 = fmaf(x.z, y.z, d0);
            d0 = fmaf(x.w, y.w, d0);
        }
        pp = lse - d0 * INV_T;
    }

    sh[threadIdx.x] = pp;
    __syncthreads();
    #pragma unroll
    for (int o = 64; o > 0; o >>= 1) {
        if (threadIdx.x < o) sh[threadIdx.x] += sh[threadIdx.x + o];
        __syncthreads();
    }
    if (threadIdx.x == 0) g_bs[blockIdx.x] = sh[0];
}

__global__ void lse_reduce(float* __restrict__ out) {
    const int t = threadIdx.x;
    float v = (t < 32) ? g_bs[t] : 0.0f;
    #pragma unroll
    for (int o = 16; o > 0; o >>= 1)
        v += __shfl_xor_sync(0xffffffffu, v, o);
    if (t == 0) out[0] = v * (1.0f / 4080.0f);
}

// ---------------------------------------------------------------------------
extern "C" void kernel_launch(void* const* d_in, const int* in_sizes, int n_in,
                              void* d_out, int out_size) {
    const float* z   = nullptr;
    const float* mem = nullptr;
    for (int i = 0; i < n_in; ++i) {
        if (in_sizes[i] == NROWS * DDIM && !z)   z   = (const float*)d_in[i];
        if (in_sizes[i] == KMEM * DDIM  && !mem) mem = (const float*)d_in[i];
    }
    if (!z)   z   = (const float*)d_in[0];
    if (!mem) mem = (const float*)d_in[2];

    cudaFuncSetAttribute(lse_mma, cudaFuncAttributeMaxDynamicSharedMemorySize,
                         SMEM_DYN);
    prep<<<(WROWS * 8 + 255) / 256, 256>>>(z, mem);
    lse_mma<<<dim3(32, SPLITS), 256, SMEM_DYN>>>();
    lse_finalize<<<32, 128>>>(z);
    lse_reduce<<<1, 32>>>((float*)d_out);
}

// round 8
// speedup vs baseline: 1.3608x; 1.0600x over previous
#include <cuda_runtime.h>
#include <math.h>
#include <stdint.h>

// ---------------- problem constants ----------------
#define NROWS  4096
#define DDIM   256
#define KMEM   16384
#define ZCOLS  4096
#define WROWS  (ZCOLS + KMEM)   // 20480
#define LSEQ   256
#define SPLITS 9                // 80 col tiles of 256: 8x9 + 1x8
#define TMR    128
#define TNC    256
#define SA     260              // A smem stride (words); ==4 mod 32
#define INV_T  (1.0f/0.07f)
#define LOG2E  1.4426950408889634f
#define LN2F   0.6931471805599453f
#define NEG_BIG (-1.0e30f)

#define SMEM_DYN (TMR * SA * 4)   // 133,120 B (A tile only)

// ---------------- scratch ----------------
// tf32, chunk-permuted for sector-perfect B loads:
//   word-in-chunk = hf*16 + qc*4 + e
__device__ uint32_t g_wp[(size_t)WROWS * DDIM];
__device__ float g_pm[SPLITS * NROWS];
__device__ float g_ps[SPLITS * NROWS];
__device__ float g_bs[32];

// ---------------- helpers ----------------
__device__ __forceinline__ uint32_t f2tf(float x) {
    uint32_t r; asm("cvt.rna.tf32.f32 %0, %1;" : "=r"(r) : "f"(x)); return r;
}
__device__ __forceinline__ float ex2f(float x) {
    float r; asm("ex2.approx.f32 %0, %1;" : "=f"(r) : "f"(x)); return r;
}
__device__ __forceinline__ void mma8(float* d,
                                     uint32_t a0, uint32_t a1, uint32_t a2, uint32_t a3,
                                     uint32_t b0, uint32_t b1) {
    asm volatile(
        "mma.sync.aligned.m16n8k8.row.col.f32.tf32.tf32.f32 "
        "{%0,%1,%2,%3}, {%4,%5,%6,%7}, {%8,%9}, {%0,%1,%2,%3};"
        : "+f"(d[0]), "+f"(d[1]), "+f"(d[2]), "+f"(d[3])
        : "r"(a0), "r"(a1), "r"(a2), "r"(a3), "r"(b0), "r"(b1));
}

// ---------------------------------------------------------------------------
// Pre-pass: tf32-convert z||mem; per-32k-chunk layout = [hf][qc][4 words].
// ---------------------------------------------------------------------------
__global__ __launch_bounds__(256)
void prep(const float* __restrict__ z, const float* __restrict__ mem) {
    const int idx = blockIdx.x * 256 + threadIdx.x;
    const int row = idx >> 3;
    const int ch  = idx & 7;
    if (row >= WROWS) return;
    const float* src = ((row < ZCOLS) ? (z + (size_t)row * DDIM)
                                      : (mem + (size_t)(row - ZCOLS) * DDIM)) + ch * 32;
    float in[32];
    #pragma unroll
    for (int q = 0; q < 8; ++q)
        *(float4*)(in + q * 4) = *(const float4*)(src + q * 4);
    uint32_t* dst = g_wp + (size_t)row * DDIM + ch * 32;
    #pragma unroll
    for (int u = 0; u < 8; ++u) {
        const int hf = u >> 2, qc = u & 3;
        uint4 o;
        o.x = f2tf(in[(hf * 2 + 0) * 8 + qc]);
        o.y = f2tf(in[(hf * 2 + 0) * 8 + qc + 4]);
        o.z = f2tf(in[(hf * 2 + 1) * 8 + qc]);
        o.w = f2tf(in[(hf * 2 + 1) * 8 + qc + 4]);
        *(uint4*)(dst + u * 4) = o;
    }
}

// ---------------------------------------------------------------------------
// Fused tf32 mma.sync GEMM + online logsumexp.
// 256 threads = 8 warps, 2(M) x 4(N); warp tile 64x64. Barrier-free main loop.
// NEW: SMSP-paired warps (wm=0 vs wm=1) walk the tile list with a half-length
// rotation so one warp's epilogue overlaps the other's GEMM on the same SMSP.
// ---------------------------------------------------------------------------
__global__ __launch_bounds__(256, 1)
void lse_mma() {
    extern __shared__ uint32_t As[];    // [128][SA]
    __shared__ float red_m[8][64];
    __shared__ float red_s[8][64];

    const int tid  = threadIdx.x;
    const int wid  = tid >> 5;
    const int lane = tid & 31;
    const int wm   = wid >> 2;          // 0..1 (M) — SMSP pair differs in wm
    const int wn   = wid & 3;           // 0..3 (N)
    const int qr   = lane >> 2;         // 0..7
    const int qc   = lane & 3;          // 0..3
    const int m0   = blockIdx.x * TMR;
    const int s    = blockIdx.y;
    const int lo   = s * 9;
    const int nt   = (s < 8) ? 9 : 8;
    const int rot  = wm ? (nt >> 1) : 0;   // stagger offset per warp group

    // ---- A tile copy with quad remap (smem quad d = qc*2+hf layout) ----
    #pragma unroll 4
    for (int it = 0; it < 32; ++it) {
        int idx = it * 256 + tid;           // uint4 index 0..8191
        int m   = idx >> 6;
        int kq  = idx & 63;
        int d   = kq & 7;
        int sq  = (kq & ~7) | (((d & 1) << 2) | (d >> 1));
        uint4 v = *(const uint4*)(g_wp + (size_t)(m0 + m) * DDIM + sq * 4);
        *(uint4*)(As + m * SA + kq * 4) = v;
    }
    __syncthreads();                        // the ONLY barrier before the end

    float rm[8], rs[8];
    #pragma unroll
    for (int i = 0; i < 8; ++i) { rm[i] = NEG_BIG; rs[i] = 0.0f; }

    const float Cs = INV_T * LOG2E;

    #pragma unroll 1
    for (int tj = 0; tj < nt; ++tj) {
        int ti = tj + rot; if (ti >= nt) ti -= nt;   // rotated order
        const int  c0 = (lo + ti) * TNC;
        const bool zp = (c0 < ZCOLS);

        const uint32_t* bp = g_wp + (size_t)(c0 + wn * 64 + qr) * DDIM + qc * 4;

        float acc[4][8][4];
        #pragma unroll
        for (int a = 0; a < 4; ++a)
            #pragma unroll
            for (int b = 0; b < 8; ++b)
                #pragma unroll
                for (int c = 0; c < 4; ++c) acc[a][b][c] = 0.0f;

        uint4 bq[2][8];
        #pragma unroll
        for (int ni = 0; ni < 8; ++ni)      // prologue: (kc=0, hf=0)
            bq[0][ni] = *(const uint4*)(bp + ni * 8 * DDIM);

        #pragma unroll 2
        for (int kc = 0; kc < 8; ++kc) {
            #pragma unroll
            for (int hf = 0; hf < 2; ++hf) {
                const int idx = kc * 2 + hf;
                const int cur = idx & 1;
                if (idx < 15) {             // prefetch next half-chunk
                    const int nk = (idx + 1) >> 1;
                    const int nh = (idx + 1) & 1;
                    const int no = nk * 32 + nh * 16;
                    #pragma unroll
                    for (int ni = 0; ni < 8; ++ni)
                        bq[cur ^ 1][ni] = *(const uint4*)(bp + ni * 8 * DDIM + no);
                }
                const int ao = kc * 32 + qc * 8 + hf * 4;
                uint4 aL[4], aH[4];
                #pragma unroll
                for (int mi = 0; mi < 4; ++mi) {
                    const int r = wm * 64 + mi * 16 + qr;
                    aL[mi] = *(const uint4*)(As + r * SA + ao);
                    aH[mi] = *(const uint4*)(As + (r + 8) * SA + ao);
                }
                #pragma unroll
                for (int mi = 0; mi < 4; ++mi)
                    #pragma unroll
                    for (int ni = 0; ni < 8; ++ni) {
                        mma8(acc[mi][ni], aL[mi].x, aH[mi].x, aL[mi].y, aH[mi].y,
                             bq[cur][ni].x, bq[cur][ni].y);
                        mma8(acc[mi][ni], aL[mi].z, aH[mi].z, aL[mi].w, aH[mi].w,
                             bq[cur][ni].z, bq[cur][ni].w);
                    }
            }
        }

        // ---- flash-LSE epilogue (per-warp, no barriers) ----
        const bool dflag = zp && (c0 == (m0 & ~(TNC - 1)));
        #pragma unroll
        for (int mi = 0; mi < 4; ++mi) {
            #pragma unroll
            for (int h = 0; h < 2; ++h) {
                const int lr   = wm * 64 + mi * 16 + h * 8 + qr;
                const int grow = m0 + lr;
                float v[16];
                float mx = NEG_BIG;
                #pragma unroll
                for (int ni = 0; ni < 8; ++ni) {
                    #pragma unroll
                    for (int c = 0; c < 2; ++c) {
                        float x = acc[mi][ni][h * 2 + c] * Cs;
                        if (dflag) {
                            const int gcol = c0 + wn * 64 + ni * 8 + 2 * qc + c;
                            if (gcol == grow) x = NEG_BIG;
                        }
                        v[ni * 2 + c] = x;
                        mx = fmaxf(mx, x);
                    }
                }
                mx = fmaxf(mx, __shfl_xor_sync(0xffffffffu, mx, 1));
                mx = fmaxf(mx, __shfl_xor_sync(0xffffffffu, mx, 2));
                float sc = 0.0f;
                #pragma unroll
                for (int j = 0; j < 16; ++j) sc += ex2f(v[j] - mx);
                sc += __shfl_xor_sync(0xffffffffu, sc, 1);
                sc += __shfl_xor_sync(0xffffffffu, sc, 2);
                const int ri = mi * 2 + h;
                const float mn = fmaxf(rm[ri], mx);
                rs[ri] = rs[ri] * ex2f(rm[ri] - mn) + sc * ex2f(mx - mn);
                rm[ri] = mn;
            }
        }
    }

    // ---- cross-warp (N-dim) merge via smem ----
    if (qc == 0) {
        #pragma unroll
        for (int mi = 0; mi < 4; ++mi)
            #pragma unroll
            for (int h = 0; h < 2; ++h) {
                const int lrw = mi * 16 + h * 8 + qr;
                red_m[wid][lrw] = rm[mi * 2 + h];
                red_s[wid][lrw] = rs[mi * 2 + h];
            }
    }
    __syncthreads();
    if (tid < 128) {
        const int wmm = tid >> 6, ri = tid & 63;
        float m = red_m[wmm * 4][ri];
        #pragma unroll
        for (int w = 1; w < 4; ++w) m = fmaxf(m, red_m[wmm * 4 + w][ri]);
        float ss = 0.0f;
        #pragma unroll
        for (int w = 0; w < 4; ++w)
            ss += red_s[wmm * 4 + w][ri] * ex2f(red_m[wmm * 4 + w][ri] - m);
        g_pm[s * NROWS + m0 + tid] = m;
        g_ps[s * NROWS + m0 + tid] = ss;
    }
}

// ---------------------------------------------------------------------------
__global__ void lse_finalize(const float* __restrict__ z) {
    __shared__ float sh[128];
    const int i = blockIdx.x * 128 + threadIdx.x;

    float m = g_pm[i];
    #pragma unroll
    for (int s2 = 1; s2 < SPLITS; ++s2)
        m = fmaxf(m, g_pm[s2 * NROWS + i]);
    float ss = 0.0f;
    #pragma unroll
    for (int s2 = 0; s2 < SPLITS; ++s2)
        ss += g_ps[s2 * NROWS + i] * ex2f(g_pm[s2 * NROWS + i] - m);
    const float lse = (m + log2f(ss)) * LN2F;

    const bool valid = (i < NROWS - 1) && ((i & (LSEQ - 1)) != (LSEQ - 1));
    float pp = 0.0f;
    if (valid) {
        const float4* a = (const float4*)(z + (size_t)i * DDIM);
        const float4* b = (const float4*)(z + (size_t)(i + 1) * DDIM);
        float d0 = 0.0f;
        #pragma unroll 8
        for (int k = 0; k < DDIM / 4; ++k) {
            float4 x = a[k], y = b[k];
            d0 = fmaf(x.x, y.x, d0);
            d0 = fmaf(x.y, y.y, d0);
            d0 = fmaf(x.z, y.z, d0);
            d0 = fmaf(x.w, y.w, d0);
        }
        pp = lse - d0 * INV_T;
    }

    sh[threadIdx.x] = pp;
    __syncthreads();
    #pragma unroll
    for (int o = 64; o > 0; o >>= 1) {
        if (threadIdx.x < o) sh[threadIdx.x] += sh[threadIdx.x + o];
        __syncthreads();
    }
    if (threadIdx.x == 0) g_bs[blockIdx.x] = sh[0];
}

__global__ void lse_reduce(float* __restrict__ out) {
    const int t = threadIdx.x;
    float v = (t < 32) ? g_bs[t] : 0.0f;
    #pragma unroll
    for (int o = 16; o > 0; o >>= 1)
        v += __shfl_xor_sync(0xffffffffu, v, o);
    if (t == 0) out[0] = v * (1.0f / 4080.0f);
}

// ---------------------------------------------------------------------------
extern "C" void kernel_launch(void* const* d_in, const int* in_sizes, int n_in,
                              void* d_out, int out_size) {
    const float* z   = nullptr;
    const float* mem = nullptr;
    for (int i = 0; i < n_in; ++i) {
        if (in_sizes[i] == NROWS * DDIM && !z)   z   = (const float*)d_in[i];
        if (in_sizes[i] == KMEM * DDIM  && !mem) mem = (const float*)d_in[i];
    }
    if (!z)   z   = (const float*)d_in[0];
    if (!mem) mem = (const float*)d_in[2];

    cudaFuncSetAttribute(lse_mma, cudaFuncAttributeMaxDynamicSharedMemorySize,
                         SMEM_DYN);
    prep<<<(WROWS * 8 + 255) / 256, 256>>>(z, mem);
    lse_mma<<<dim3(32, SPLITS), 256, SMEM_DYN>>>();
    lse_finalize<<<32, 128>>>(z);
    lse_reduce<<<1, 32>>>((float*)d_out);
}

// round 9
// speedup vs baseline: 2.1743x; 1.5978x over previous
#include <cuda_runtime.h>
#include <math.h>
#include <stdint.h>

// ---------------- problem constants ----------------
#define NROWS  4096
#define DDIM   256
#define KMEM   16384
#define ZCOLS  4096
#define WROWS  (ZCOLS + KMEM)   // 20480
#define LSEQ   256
#define SPLITS 9                // 80 col tiles of 256: 8x9 + 1x8
#define TMR    128
#define TNC    256
#define WPR    128              // words per row (bf16 packed: 256 k / 2)
#define SA     132              // A smem stride (words); ==4 mod 32
#define INV_T  (1.0f/0.07f)
#define LOG2E  1.4426950408889634f
#define LN2F   0.6931471805599453f
#define NEG_BIG (-1.0e30f)

#define SMEM_DYN (TMR * SA * 4)   // 67,584 B

// ---------------- scratch ----------------
// bf16-packed (k even low / k odd high), per-32k-chunk lane-fragment layout:
//   word-in-chunk = qc*4 + e, e in {g0.qc, g0.qc+4, g1.qc, g1.qc+4}
__device__ uint32_t g_wp[(size_t)WROWS * WPR];
__device__ float g_pm[SPLITS * NROWS];
__device__ float g_ps[SPLITS * NROWS];
__device__ float g_bs[32];

// ---------------- helpers ----------------
__device__ __forceinline__ uint32_t packbf(float lo, float hi) {
    uint32_t r;
    asm("cvt.rn.bf16x2.f32 %0, %1, %2;" : "=r"(r) : "f"(hi), "f"(lo));
    return r;   // low half = lo (even k), high half = hi (odd k)
}
__device__ __forceinline__ float ex2f(float x) {
    float r; asm("ex2.approx.f32 %0, %1;" : "=f"(r) : "f"(x)); return r;
}
__device__ __forceinline__ void mma16(float* d,
                                      uint32_t a0, uint32_t a1, uint32_t a2, uint32_t a3,
                                      uint32_t b0, uint32_t b1) {
    asm volatile(
        "mma.sync.aligned.m16n8k16.row.col.f32.bf16.bf16.f32 "
        "{%0,%1,%2,%3}, {%4,%5,%6,%7}, {%8,%9}, {%0,%1,%2,%3};"
        : "+f"(d[0]), "+f"(d[1]), "+f"(d[2]), "+f"(d[3])
        : "r"(a0), "r"(a1), "r"(a2), "r"(a3), "r"(b0), "r"(b1));
}

// ---------------------------------------------------------------------------
// Pre-pass: bf16-convert z||mem into the lane-fragment layout.
// One thread per (row, 32k-chunk): 32 floats in -> 16 words (4 uint4) out.
// ---------------------------------------------------------------------------
__global__ __launch_bounds__(256)
void prep(const float* __restrict__ z, const float* __restrict__ mem) {
    const int idx = blockIdx.x * 256 + threadIdx.x;
    const int row = idx >> 3;
    const int ch  = idx & 7;
    if (row >= WROWS) return;
    const float* src = ((row < ZCOLS) ? (z + (size_t)row * DDIM)
                                      : (mem + (size_t)(row - ZCOLS) * DDIM)) + ch * 32;
    float in[32];
    #pragma unroll
    for (int q = 0; q < 8; ++q)
        *(float4*)(in + q * 4) = *(const float4*)(src + q * 4);
    uint32_t* dst = g_wp + (size_t)row * WPR + ch * 16;
    #pragma unroll
    for (int qc = 0; qc < 4; ++qc) {
        uint4 o;
        o.x = packbf(in[2 * qc],          in[2 * qc + 1]);        // g0, word qc
        o.y = packbf(in[2 * qc + 8],      in[2 * qc + 9]);        // g0, word qc+4
        o.z = packbf(in[16 + 2 * qc],     in[16 + 2 * qc + 1]);   // g1, word qc
        o.w = packbf(in[16 + 2 * qc + 8], in[16 + 2 * qc + 9]);   // g1, word qc+4
        *(uint4*)(dst + qc * 4) = o;
    }
}

// ---------------------------------------------------------------------------
// Fused bf16 mma.sync GEMM + online logsumexp.
// 256 threads = 8 warps, 2(M) x 4(N); warp tile 64x64 (m16n8k16).
// Barrier-free main loop; SMSP-paired warps staggered by nt/2 tiles.
// ---------------------------------------------------------------------------
__global__ __launch_bounds__(256, 1)
void lse_mma() {
    extern __shared__ uint32_t As[];    // [128][SA]; superchunk quad d = qc*2+c
    __shared__ float red_m[8][64];
    __shared__ float red_s[8][64];

    const int tid  = threadIdx.x;
    const int wid  = tid >> 5;
    const int lane = tid & 31;
    const int wm   = wid >> 2;          // 0..1 (M)
    const int wn   = wid & 3;           // 0..3 (N)
    const int qr   = lane >> 2;         // 0..7
    const int qc   = lane & 3;          // 0..3
    const int m0   = blockIdx.x * TMR;
    const int s    = blockIdx.y;
    const int lo   = s * 9;
    const int nt   = (s < 8) ? 9 : 8;
    const int rot  = wm ? (nt >> 1) : 0;

    // ---- A tile copy with quad remap: dest quad d=qc*2+c <- src quad c*4+qc
    #pragma unroll 4
    for (int it = 0; it < 16; ++it) {
        int idx = it * 256 + tid;           // uint4 index 0..4095
        int m   = idx >> 5;
        int kq  = idx & 31;                 // dest quad within row
        int d   = kq & 7;
        int sq  = (kq & ~7) | (((d & 1) << 2) | (d >> 1));
        uint4 v = *(const uint4*)(g_wp + (size_t)(m0 + m) * WPR + sq * 4);
        *(uint4*)(As + m * SA + kq * 4) = v;
    }
    __syncthreads();                        // the ONLY barrier before the end

    float rm[8], rs[8];
    #pragma unroll
    for (int i = 0; i < 8; ++i) { rm[i] = NEG_BIG; rs[i] = 0.0f; }

    const float Cs = INV_T * LOG2E;

    #pragma unroll 1
    for (int tj = 0; tj < nt; ++tj) {
        int ti = tj + rot; if (ti >= nt) ti -= nt;
        const int  c0 = (lo + ti) * TNC;
        const bool zp = (c0 < ZCOLS);

        const uint32_t* bp = g_wp + (size_t)(c0 + wn * 64 + qr) * WPR + qc * 4;

        float acc[4][8][4];
        #pragma unroll
        for (int a = 0; a < 4; ++a)
            #pragma unroll
            for (int b = 0; b < 8; ++b)
                #pragma unroll
                for (int c = 0; c < 4; ++c) acc[a][b][c] = 0.0f;

        uint4 bq[2][8];
        #pragma unroll
        for (int ni = 0; ni < 8; ++ni)      // prologue: chunk 0
            bq[0][ni] = *(const uint4*)(bp + ni * 8 * WPR);

        #pragma unroll 2
        for (int kc = 0; kc < 8; ++kc) {
            const int cur = kc & 1;
            if (kc < 7) {                   // prefetch next 32k chunk
                #pragma unroll
                for (int ni = 0; ni < 8; ++ni)
                    bq[cur ^ 1][ni] =
                        *(const uint4*)(bp + ni * 8 * WPR + (kc + 1) * 16);
            }
            const int ao = (kc >> 1) * 32 + qc * 8 + (kc & 1) * 4;
            uint4 aL[4], aH[4];
            #pragma unroll
            for (int mi = 0; mi < 4; ++mi) {
                const int r = wm * 64 + mi * 16 + qr;
                aL[mi] = *(const uint4*)(As + r * SA + ao);
                aH[mi] = *(const uint4*)(As + (r + 8) * SA + ao);
            }
            #pragma unroll
            for (int mi = 0; mi < 4; ++mi)
                #pragma unroll
                for (int ni = 0; ni < 8; ++ni) {
                    mma16(acc[mi][ni], aL[mi].x, aH[mi].x, aL[mi].y, aH[mi].y,
                          bq[cur][ni].x, bq[cur][ni].y);
                    mma16(acc[mi][ni], aL[mi].z, aH[mi].z, aL[mi].w, aH[mi].w,
                          bq[cur][ni].z, bq[cur][ni].w);
                }
        }

        // ---- flash-LSE epilogue (per-warp, no barriers) ----
        const bool dflag = zp && (c0 == (m0 & ~(TNC - 1)));
        #pragma unroll
        for (int mi = 0; mi < 4; ++mi) {
            #pragma unroll
            for (int h = 0; h < 2; ++h) {
                const int lr   = wm * 64 + mi * 16 + h * 8 + qr;
                const int grow = m0 + lr;
                float v[16];
                float mx = NEG_BIG;
                #pragma unroll
                for (int ni = 0; ni < 8; ++ni) {
                    #pragma unroll
                    for (int c = 0; c < 2; ++c) {
                        float x = acc[mi][ni][h * 2 + c] * Cs;
                        if (dflag) {
                            const int gcol = c0 + wn * 64 + ni * 8 + 2 * qc + c;
                            if (gcol == grow) x = NEG_BIG;
                        }
                        v[ni * 2 + c] = x;
                        mx = fmaxf(mx, x);
                    }
                }
                mx = fmaxf(mx, __shfl_xor_sync(0xffffffffu, mx, 1));
                mx = fmaxf(mx, __shfl_xor_sync(0xffffffffu, mx, 2));
                float sc = 0.0f;
                #pragma unroll
                for (int j = 0; j < 16; ++j) sc += ex2f(v[j] - mx);
                sc += __shfl_xor_sync(0xffffffffu, sc, 1);
                sc += __shfl_xor_sync(0xffffffffu, sc, 2);
                const int ri = mi * 2 + h;
                const float mn = fmaxf(rm[ri], mx);
                rs[ri] = rs[ri] * ex2f(rm[ri] - mn) + sc * ex2f(mx - mn);
                rm[ri] = mn;
            }
        }
    }

    // ---- cross-warp (N-dim) merge via smem ----
    if (qc == 0) {
        #pragma unroll
        for (int mi = 0; mi < 4; ++mi)
            #pragma unroll
            for (int h = 0; h < 2; ++h) {
                const int lrw = mi * 16 + h * 8 + qr;
                red_m[wid][lrw] = rm[mi * 2 + h];
                red_s[wid][lrw] = rs[mi * 2 + h];
            }
    }
    __syncthreads();
    if (tid < 128) {
        const int wmm = tid >> 6, ri = tid & 63;
        float m = red_m[wmm * 4][ri];
        #pragma unroll
        for (int w = 1; w < 4; ++w) m = fmaxf(m, red_m[wmm * 4 + w][ri]);
        float ss = 0.0f;
        #pragma unroll
        for (int w = 0; w < 4; ++w)
            ss += red_s[wmm * 4 + w][ri] * ex2f(red_m[wmm * 4 + w][ri] - m);
        g_pm[s * NROWS + m0 + tid] = m;
        g_ps[s * NROWS + m0 + tid] = ss;
    }
}

// ---------------------------------------------------------------------------
__global__ void lse_finalize(const float* __restrict__ z) {
    __shared__ float sh[128];
    const int i = blockIdx.x * 128 + threadIdx.x;

    float m = g_pm[i];
    #pragma unroll
    for (int s2 = 1; s2 < SPLITS; ++s2)
        m = fmaxf(m, g_pm[s2 * NROWS + i]);
    float ss = 0.0f;
    #pragma unroll
    for (int s2 = 0; s2 < SPLITS; ++s2)
        ss += g_ps[s2 * NROWS + i] * ex2f(g_pm[s2 * NROWS + i] - m);
    const float lse = (m + log2f(ss)) * LN2F;

    const bool valid = (i < NROWS - 1) && ((i & (LSEQ - 1)) != (LSEQ - 1));
    float pp = 0.0f;
    if (valid) {
        const float4* a = (const float4*)(z + (size_t)i * DDIM);
        const float4* b = (const float4*)(z + (size_t)(i + 1) * DDIM);
        float d0 = 0.0f;
        #pragma unroll 8
        for (int k = 0; k < DDIM / 4; ++k) {
            float4 x = a[k], y = b[k];
            d0 = fmaf(x.x, y.x, d0);
            d0 = fmaf(x.y, y.y, d0);
            d0 = fmaf(x.z, y.z, d0);
            d0 = fmaf(x.w, y.w, d0);
        }
        pp = lse - d0 * INV_T;
    }

    sh[threadIdx.x] = pp;
    __syncthreads();
    #pragma unroll
    for (int o = 64; o > 0; o >>= 1) {
        if (threadIdx.x < o) sh[threadIdx.x] += sh[threadIdx.x + o];
        __syncthreads();
    }
    if (threadIdx.x == 0) g_bs[blockIdx.x] = sh[0];
}

__global__ void lse_reduce(float* __restrict__ out) {
    const int t = threadIdx.x;
    float v = (t < 32) ? g_bs[t] : 0.0f;
    #pragma unroll
    for (int o = 16; o > 0; o >>= 1)
        v += __shfl_xor_sync(0xffffffffu, v, o);
    if (t == 0) out[0] = v * (1.0f / 4080.0f);
}

// ---------------------------------------------------------------------------
extern "C" void kernel_launch(void* const* d_in, const int* in_sizes, int n_in,
                              void* d_out, int out_size) {
    const float* z   = nullptr;
    const float* mem = nullptr;
    for (int i = 0; i < n_in; ++i) {
        if (in_sizes[i] == NROWS * DDIM && !z)   z   = (const float*)d_in[i];
        if (in_sizes[i] == KMEM * DDIM  && !mem) mem = (const float*)d_in[i];
    }
    if (!z)   z   = (const float*)d_in[0];
    if (!mem) mem = (const float*)d_in[2];

    cudaFuncSetAttribute(lse_mma, cudaFuncAttributeMaxDynamicSharedMemorySize,
                         SMEM_DYN);
    prep<<<(WROWS * 8 + 255) / 256, 256>>>(z, mem);
    lse_mma<<<dim3(32, SPLITS), 256, SMEM_DYN>>>();
    lse_finalize<<<32, 128>>>(z);
    lse_reduce<<<1, 32>>>((float*)d_out);
}

// round 10
// speedup vs baseline: 2.2354x; 1.0281x over previous
#include <cuda_runtime.h>
#include <math.h>
#include <stdint.h>

// ---------------- problem constants ----------------
#define NROWS  4096
#define DDIM   256
#define KMEM   16384
#define ZCOLS  4096
#define WROWS  (ZCOLS + KMEM)   // 20480
#define LSEQ   256
#define SPLITS 9                // 80 col tiles of 256: 8x9 + 1x8
#define TMR    128
#define TNC    256
#define WPR    128              // words per row (bf16 packed: 256 k / 2)
#define SA     132              // A smem stride (words); ==4 mod 32
#define INV_T  (1.0f/0.07f)
#define LOG2E  1.4426950408889634f
#define LN2F   0.6931471805599453f
#define NEG_BIG (-1.0e30f)

#define SMEM_DYN (TMR * SA * 4)   // 67,584 B

// ---------------- scratch ----------------
// bf16-packed (k even low / k odd high), per-32k-chunk lane-fragment layout:
//   word-in-chunk = qc*4 + e, e in {g0.qc, g0.qc+4, g1.qc, g1.qc+4}
__device__ uint32_t g_wp[(size_t)WROWS * WPR];
__device__ float g_pm[SPLITS * NROWS];
__device__ float g_ps[SPLITS * NROWS];
__device__ float g_bs[32];

// ---------------- helpers ----------------
__device__ __forceinline__ uint32_t packbf(float lo, float hi) {
    uint32_t r;
    asm("cvt.rn.bf16x2.f32 %0, %1, %2;" : "=r"(r) : "f"(hi), "f"(lo));
    return r;   // low half = lo (even k), high half = hi (odd k)
}
__device__ __forceinline__ float ex2f(float x) {
    float r; asm("ex2.approx.f32 %0, %1;" : "=f"(r) : "f"(x)); return r;
}
__device__ __forceinline__ void mma16(float* d,
                                      uint32_t a0, uint32_t a1, uint32_t a2, uint32_t a3,
                                      uint32_t b0, uint32_t b1) {
    asm volatile(
        "mma.sync.aligned.m16n8k16.row.col.f32.bf16.bf16.f32 "
        "{%0,%1,%2,%3}, {%4,%5,%6,%7}, {%8,%9}, {%0,%1,%2,%3};"
        : "+f"(d[0]), "+f"(d[1]), "+f"(d[2]), "+f"(d[3])
        : "r"(a0), "r"(a1), "r"(a2), "r"(a3), "r"(b0), "r"(b1));
}

// ---------------------------------------------------------------------------
// Pre-pass: bf16-convert z||mem into the lane-fragment layout.
// ---------------------------------------------------------------------------
__global__ __launch_bounds__(256)
void prep(const float* __restrict__ z, const float* __restrict__ mem) {
    const int idx = blockIdx.x * 256 + threadIdx.x;
    const int row = idx >> 3;
    const int ch  = idx & 7;
    if (row >= WROWS) return;
    const float* src = ((row < ZCOLS) ? (z + (size_t)row * DDIM)
                                      : (mem + (size_t)(row - ZCOLS) * DDIM)) + ch * 32;
    float in[32];
    #pragma unroll
    for (int q = 0; q < 8; ++q)
        *(float4*)(in + q * 4) = *(const float4*)(src + q * 4);
    uint32_t* dst = g_wp + (size_t)row * WPR + ch * 16;
    #pragma unroll
    for (int qc = 0; qc < 4; ++qc) {
        uint4 o;
        o.x = packbf(in[2 * qc],          in[2 * qc + 1]);
        o.y = packbf(in[2 * qc + 8],      in[2 * qc + 9]);
        o.z = packbf(in[16 + 2 * qc],     in[16 + 2 * qc + 1]);
        o.w = packbf(in[16 + 2 * qc + 8], in[16 + 2 * qc + 9]);
        *(uint4*)(dst + qc * 4) = o;
    }
}

// ---------------------------------------------------------------------------
// Fused bf16 mma.sync GEMM + online logsumexp.
// 256 threads = 8 warps, 2(M) x 4(N); warp tile 64x64 (m16n8k16).
// Barrier-free main loop; SMSP-paired warps staggered by nt/2 tiles.
// Continuous cross-tile B prefetch: the LDG chain never goes cold.
// ---------------------------------------------------------------------------
__global__ __launch_bounds__(256, 1)
void lse_mma() {
    extern __shared__ uint32_t As[];    // [128][SA]
    __shared__ float red_m[8][64];
    __shared__ float red_s[8][64];

    const int tid  = threadIdx.x;
    const int wid  = tid >> 5;
    const int lane = tid & 31;
    const int wm   = wid >> 2;          // 0..1 (M)
    const int wn   = wid & 3;           // 0..3 (N)
    const int qr   = lane >> 2;         // 0..7
    const int qc   = lane & 3;          // 0..3
    const int m0   = blockIdx.x * TMR;
    const int s    = blockIdx.y;
    const int lo   = s * 9;
    const int nt   = (s < 8) ? 9 : 8;
    const int rot  = wm ? (nt >> 1) : 0;

    const int broff = wn * 64 + qr;     // B row offset within tile
    const int bwoff = qc * 4;           // B word offset (lane fragment)

    // first tile in this warp's rotated order; issue its chunk-0 LDGs NOW so
    // they complete under the A-tile copy below.
    int ti = rot;
    const uint32_t* bp = g_wp + (size_t)((lo + ti) * TNC + broff) * WPR + bwoff;
    uint4 bq[2][8];
    #pragma unroll
    for (int ni = 0; ni < 8; ++ni)
        bq[0][ni] = *(const uint4*)(bp + ni * 8 * WPR);

    // ---- A tile copy with quad remap: dest quad d=qc*2+c <- src quad c*4+qc
    #pragma unroll 4
    for (int it = 0; it < 16; ++it) {
        int idx = it * 256 + tid;           // uint4 index 0..4095
        int m   = idx >> 5;
        int kq  = idx & 31;
        int d   = kq & 7;
        int sq  = (kq & ~7) | (((d & 1) << 2) | (d >> 1));
        uint4 v = *(const uint4*)(g_wp + (size_t)(m0 + m) * WPR + sq * 4);
        *(uint4*)(As + m * SA + kq * 4) = v;
    }
    __syncthreads();                        // the ONLY barrier before the end

    float rm[8], rs[8];
    #pragma unroll
    for (int i = 0; i < 8; ++i) { rm[i] = NEG_BIG; rs[i] = 0.0f; }

    const float Cs = INV_T * LOG2E;

    #pragma unroll 1
    for (int tj = 0; tj < nt; ++tj) {
        const int  c0 = (lo + ti) * TNC;
        const bool zp = (c0 < ZCOLS);

        // next tile (rotated order) for the cross-tile prefetch
        int tn = ti + 1; if (tn >= nt) tn = 0;
        const uint32_t* bpn = g_wp + (size_t)((lo + tn) * TNC + broff) * WPR + bwoff;

        float acc[4][8][4];
        #pragma unroll
        for (int a = 0; a < 4; ++a)
            #pragma unroll
            for (int b = 0; b < 8; ++b)
                #pragma unroll
                for (int c = 0; c < 4; ++c) acc[a][b][c] = 0.0f;

        #pragma unroll 2
        for (int kc = 0; kc < 8; ++kc) {
            const int cur = kc & 1;
            if (kc < 7) {                   // prefetch next chunk of this tile
                #pragma unroll
                for (int ni = 0; ni < 8; ++ni)
                    bq[cur ^ 1][ni] =
                        *(const uint4*)(bp + ni * 8 * WPR + (kc + 1) * 16);
            } else if (tj + 1 < nt) {       // prefetch NEXT TILE's chunk 0
                #pragma unroll
                for (int ni = 0; ni < 8; ++ni)
                    bq[0][ni] = *(const uint4*)(bpn + ni * 8 * WPR);
            }
            const int ao = (kc >> 1) * 32 + qc * 8 + (kc & 1) * 4;
            uint4 aL[4], aH[4];
            #pragma unroll
            for (int mi = 0; mi < 4; ++mi) {
                const int r = wm * 64 + mi * 16 + qr;
                aL[mi] = *(const uint4*)(As + r * SA + ao);
                aH[mi] = *(const uint4*)(As + (r + 8) * SA + ao);
            }
            #pragma unroll
            for (int mi = 0; mi < 4; ++mi)
                #pragma unroll
                for (int ni = 0; ni < 8; ++ni) {
                    mma16(acc[mi][ni], aL[mi].x, aH[mi].x, aL[mi].y, aH[mi].y,
                          bq[cur][ni].x, bq[cur][ni].y);
                    mma16(acc[mi][ni], aL[mi].z, aH[mi].z, aL[mi].w, aH[mi].w,
                          bq[cur][ni].z, bq[cur][ni].w);
                }
        }

        // ---- flash-LSE epilogue: max over RAW acc, scale fused into ex2 ----
        const bool dflag = zp && (c0 == (m0 & ~(TNC - 1)));
        #pragma unroll
        for (int mi = 0; mi < 4; ++mi) {
            #pragma unroll
            for (int h = 0; h < 2; ++h) {
                const int lr   = wm * 64 + mi * 16 + h * 8 + qr;
                const int grow = m0 + lr;
                float v[16];
                float mx = NEG_BIG;
                #pragma unroll
                for (int ni = 0; ni < 8; ++ni) {
                    #pragma unroll
                    for (int c = 0; c < 2; ++c) {
                        float x = acc[mi][ni][h * 2 + c];       // raw
                        if (dflag) {
                            const int gcol = c0 + wn * 64 + ni * 8 + 2 * qc + c;
                            if (gcol == grow) x = NEG_BIG;
                        }
                        v[ni * 2 + c] = x;
                        mx = fmaxf(mx, x);
                    }
                }
                mx = fmaxf(mx, __shfl_xor_sync(0xffffffffu, mx, 1));
                mx = fmaxf(mx, __shfl_xor_sync(0xffffffffu, mx, 2));
                const float mxs = mx * Cs;                      // log2 domain
                float sc = 0.0f;
                #pragma unroll
                for (int j = 0; j < 16; ++j)
                    sc += ex2f(fmaf(v[j], Cs, -mxs));
                sc += __shfl_xor_sync(0xffffffffu, sc, 1);
                sc += __shfl_xor_sync(0xffffffffu, sc, 2);
                const int ri = mi * 2 + h;
                const float mn = fmaxf(rm[ri], mxs);
                rs[ri] = rs[ri] * ex2f(rm[ri] - mn) + sc * ex2f(mxs - mn);
                rm[ri] = mn;
            }
        }

        ti = tn;
        bp = bpn;
    }

    // ---- cross-warp (N-dim) merge via smem ----
    if (qc == 0) {
        #pragma unroll
        for (int mi = 0; mi < 4; ++mi)
            #pragma unroll
            for (int h = 0; h < 2; ++h) {
                const int lrw = mi * 16 + h * 8 + qr;
                red_m[wid][lrw] = rm[mi * 2 + h];
                red_s[wid][lrw] = rs[mi * 2 + h];
            }
    }
    __syncthreads();
    if (tid < 128) {
        const int wmm = tid >> 6, ri = tid & 63;
        float m = red_m[wmm * 4][ri];
        #pragma unroll
        for (int w = 1; w < 4; ++w) m = fmaxf(m, red_m[wmm * 4 + w][ri]);
        float ss = 0.0f;
        #pragma unroll
        for (int w = 0; w < 4; ++w)
            ss += red_s[wmm * 4 + w][ri] * ex2f(red_m[wmm * 4 + w][ri] - m);
        g_pm[s * NROWS + m0 + tid] = m;
        g_ps[s * NROWS + m0 + tid] = ss;
    }
}

// ---------------------------------------------------------------------------
__global__ void lse_finalize(const float* __restrict__ z) {
    __shared__ float sh[128];
    const int i = blockIdx.x * 128 + threadIdx.x;

    float m = g_pm[i];
    #pragma unroll
    for (int s2 = 1; s2 < SPLITS; ++s2)
        m = fmaxf(m, g_pm[s2 * NROWS + i]);
    float ss = 0.0f;
    #pragma unroll
    for (int s2 = 0; s2 < SPLITS; ++s2)
        ss += g_ps[s2 * NROWS + i] * ex2f(g_pm[s2 * NROWS + i] - m);
    const float lse = (m + log2f(ss)) * LN2F;

    const bool valid = (i < NROWS - 1) && ((i & (LSEQ - 1)) != (LSEQ - 1));
    float pp = 0.0f;
    if (valid) {
        const float4* a = (const float4*)(z + (size_t)i * DDIM);
        const float4* b = (const float4*)(z + (size_t)(i + 1) * DDIM);
        float d0 = 0.0f;
        #pragma unroll 8
        for (int k = 0; k < DDIM / 4; ++k) {
            float4 x = a[k], y = b[k];
            d0 = fmaf(x.x, y.x, d0);
            d0 = fmaf(x.y, y.y, d0);
            d0 = fmaf(x.z, y.z, d0);
            d0 = fmaf(x.w, y.w, d0);
        }
        pp = lse - d0 * INV_T;
    }

    sh[threadIdx.x] = pp;
    __syncthreads();
    #pragma unroll
    for (int o = 64; o > 0; o >>= 1) {
        if (threadIdx.x < o) sh[threadIdx.x] += sh[threadIdx.x + o];
        __syncthreads();
    }
    if (threadIdx.x == 0) g_bs[blockIdx.x] = sh[0];
}

__global__ void lse_reduce(float* __restrict__ out) {
    const int t = threadIdx.x;
    float v = (t < 32) ? g_bs[t] : 0.0f;
    #pragma unroll
    for (int o = 16; o > 0; o >>= 1)
        v += __shfl_xor_sync(0xffffffffu, v, o);
    if (t == 0) out[0] = v * (1.0f / 4080.0f);
}

// ---------------------------------------------------------------------------
extern "C" void kernel_launch(void* const* d_in, const int* in_sizes, int n_in,
                              void* d_out, int out_size) {
    const float* z   = nullptr;
    const float* mem = nullptr;
    for (int i = 0; i < n_in; ++i) {
        if (in_sizes[i] == NROWS * DDIM && !z)   z   = (const float*)d_in[i];
        if (in_sizes[i] == KMEM * DDIM  && !mem) mem = (const float*)d_in[i];
    }
    if (!z)   z   = (const float*)d_in[0];
    if (!mem) mem = (const float*)d_in[2];

    cudaFuncSetAttribute(lse_mma, cudaFuncAttributeMaxDynamicSharedMemorySize,
                         SMEM_DYN);
    prep<<<(WROWS * 8 + 255) / 256, 256>>>(z, mem);
    lse_mma<<<dim3(32, SPLITS), 256, SMEM_DYN>>>();
    lse_finalize<<<32, 128>>>(z);
    lse_reduce<<<1, 32>>>((float*)d_out);
}